// round 14
// baseline (speedup 1.0000x reference)
#include <cuda_runtime.h>
#include <cuda_fp16.h>
#include <cstdint>

#define HDIM 4096
#define NEXP 64
#define BM   128
#define BK   64
#define TPAD 72      // padded halves per smem row (144B)
#define NTHR 512
#define NCHUNK (HDIM / BK)

// dynamic smem (bytes), double buffered
#define XH_OFF 0
#define XL_OFF (BM * TPAD * 2)                  // 18432
#define WH_OFF (2 * BM * TPAD * 2)              // 36864
#define W_BYTES (2 * NEXP * TPAD * 2)           // 18432 (WH|WL contiguous)
#define BUF_BYTES (WH_OFF + W_BYTES)            // 55296
#define SMEM_TOTAL (2 * BUF_BYTES)              // 110592
#define W_GRAN (W_BYTES / 16)                   // 1152 16B granules

__device__ float    g_z[128];
__device__ unsigned g_cnt = 0;
// Pre-split W, one 18432B smem-image per chunk: [WH 64x144B | WL 64x144B]
__device__ __align__(16) unsigned char g_wblob[NCHUNK * W_BYTES];

__device__ __forceinline__ void split2(float f0, float f1, unsigned& hi, unsigned& lo) {
    __half2 h = __floats2half2_rn(f0, f1);
    float2 hf = __half22float2(h);
    __half2 l = __floats2half2_rn(f0 - hf.x, f1 - hf.y);
    hi = *reinterpret_cast<unsigned*>(&h);
    lo = *reinterpret_cast<unsigned*>(&l);
}
__device__ __forceinline__ void ldsm4(unsigned* d, uint32_t addr) {
    asm volatile("ldmatrix.sync.aligned.m8n8.x4.shared.b16 {%0,%1,%2,%3}, [%4];"
                 : "=r"(d[0]), "=r"(d[1]), "=r"(d[2]), "=r"(d[3]) : "r"(addr));
}
__device__ __forceinline__ void mma16816(float* c, const unsigned* a, unsigned b0, unsigned b1) {
    asm volatile("mma.sync.aligned.m16n8k16.row.col.f32.f16.f16.f32 "
                 "{%0,%1,%2,%3}, {%4,%5,%6,%7}, {%8,%9}, {%0,%1,%2,%3};"
                 : "+f"(c[0]), "+f"(c[1]), "+f"(c[2]), "+f"(c[3])
                 : "r"(a[0]), "r"(a[1]), "r"(a[2]), "r"(a[3]), "r"(b0), "r"(b1));
}
__device__ __forceinline__ void cpa16(uint32_t dst, const unsigned char* src) {
    asm volatile("cp.async.cg.shared.global [%0], [%1], 16;" :: "r"(dst), "l"(src) : "memory");
}

// ---- W prep: split fp32 W (x64) into fp16 hi/lo smem images, once per call ----
__global__ __launch_bounds__(256) void prep_w(const float* __restrict__ W) {
    const int c   = blockIdx.x;              // chunk
    const int tid = threadIdx.x;
    const int wr  = tid >> 2;                // expert row 0..63
    const int wc  = (tid & 3) * 16;          // 16 floats
    const float* src = W + (size_t)wr * HDIM + c * BK + wc;
    unsigned char* hib = g_wblob + (size_t)c * W_BYTES + wr * (TPAD * 2) + wc * 2;
    unsigned char* lob = hib + NEXP * TPAD * 2;
    #pragma unroll
    for (int jj = 0; jj < 2; ++jj) {
        float4 a = *(const float4*)(src + 8 * jj);
        float4 b = *(const float4*)(src + 8 * jj + 4);
        uint4 hv, lv;
        split2(a.x * 64.f, a.y * 64.f, hv.x, lv.x); split2(a.z * 64.f, a.w * 64.f, hv.y, lv.y);
        split2(b.x * 64.f, b.y * 64.f, hv.z, lv.z); split2(b.z * 64.f, b.w * 64.f, hv.w, lv.w);
        *(uint4*)(hib + 16 * jj) = hv;
        *(uint4*)(lob + 16 * jj) = lv;
    }
}

__global__ __launch_bounds__(NTHR, 1) void router_mma(
    const float* __restrict__ X, float* __restrict__ out, int T)
{
    extern __shared__ char smem[];
    __shared__ float zred[BM];
    const uint32_t sb = (uint32_t)__cvta_generic_to_shared(smem);

    const int tid  = threadIdx.x;
    const int lane = tid & 31;
    const int warp = tid >> 5;          // 0..15
    const int tok0 = blockIdx.x * BM;

    // ---- X loader (same as R8) ----
    const int xr = tid >> 2, xc = (tid & 3) * 16;   // 4 thr/row, 16 floats
    const float* xg = X + (size_t)(tok0 + xr) * HDIM + xc;

    // ---- warp tiling: 8 m32n32 tiles, warp pair (w, w+8) splits k-steps ----
    const int w2 = warp & 7;
    const int m0 = (w2 & 3) * 32;
    const int n0 = (w2 >> 2) * 32;
    const int ksBase = (warp >> 3) * 2; // 0 or 2

    const int g = lane >> 3, r = lane & 7;
    uint32_t aOff[2];
    #pragma unroll
    for (int mt = 0; mt < 2; ++mt)
        aOff[mt] = (uint32_t)(((m0 + mt * 16 + r + ((g & 1) << 3)) * TPAD + ((g >> 1) << 3)) * 2);
    const int bRow = r + ((g >> 1) << 3);
    const int bK   = (g & 1) << 3;

    float acc[2][4][4];
    #pragma unroll
    for (int mt = 0; mt < 2; ++mt)
        #pragma unroll
        for (int j = 0; j < 4; ++j)
            #pragma unroll
            for (int q = 0; q < 4; ++q) acc[mt][j][q] = 0.f;

    float4 xv[4];

    // ---- prologue: W0 cp.async + X0 load/convert into buffer 0 ----
    {
        const uint32_t wdst = sb + WH_OFF;
        const unsigned char* wsrc = g_wblob;
        #pragma unroll
        for (int gi = 0; gi < 3; ++gi) {
            const int idx = tid + gi * NTHR;
            if (idx < W_GRAN) cpa16(wdst + idx * 16, wsrc + idx * 16);
        }
        asm volatile("cp.async.commit_group;" ::: "memory");
    }
    #pragma unroll
    for (int j = 0; j < 4; ++j) xv[j] = *(const float4*)(xg + j * 4);
    {
        char* buf = smem;
        #pragma unroll
        for (int jj = 0; jj < 2; ++jj) {
            float4 a = xv[2 * jj], b = xv[2 * jj + 1];
            uint4 hv, lv;
            split2(a.x, a.y, hv.x, lv.x); split2(a.z, a.w, hv.y, lv.y);
            split2(b.x, b.y, hv.z, lv.z); split2(b.z, b.w, hv.w, lv.w);
            const int off = (xr * TPAD + xc + 8 * jj) * 2;
            *(uint4*)(buf + XH_OFF + off) = hv;
            *(uint4*)(buf + XL_OFF + off) = lv;
        }
    }
    asm volatile("cp.async.wait_group 0;" ::: "memory");
    __syncthreads();

    int p = 0;
    // ---- main loop ----
    for (int kt = BK; kt <= HDIM; kt += BK) {
        if (kt < HDIM) {
            // W copy for next chunk into other buffer (overlaps with MMA below)
            const uint32_t wdst = sb + (uint32_t)((p ^ 1) * BUF_BYTES) + WH_OFF;
            const unsigned char* wsrc = g_wblob + (size_t)(kt / BK) * W_BYTES;
            #pragma unroll
            for (int gi = 0; gi < 3; ++gi) {
                const int idx = tid + gi * NTHR;
                if (idx < W_GRAN) cpa16(wdst + idx * 16, wsrc + idx * 16);
            }
            asm volatile("cp.async.commit_group;" ::: "memory");
            #pragma unroll
            for (int j = 0; j < 4; ++j) xv[j] = *(const float4*)(xg + kt + j * 4);
        }

        // MMA chunk (kt/BK - 1) on buffer p
        {
            const uint32_t base = sb + (uint32_t)(p * BUF_BYTES);
            #pragma unroll
            for (int ksi = 0; ksi < 2; ++ksi) {
                const int ks = ksBase + ksi;
                unsigned ah[2][4], al[2][4];
                #pragma unroll
                for (int mt = 0; mt < 2; ++mt) {
                    ldsm4(ah[mt], base + XH_OFF + aOff[mt] + ks * 32);
                    ldsm4(al[mt], base + XL_OFF + aOff[mt] + ks * 32);
                }
                #pragma unroll
                for (int nt = 0; nt < 2; ++nt) {
                    const uint32_t boff = (uint32_t)(((n0 + nt * 16 + bRow) * TPAD + bK) * 2 + ks * 32);
                    unsigned bh[4], bl[4];
                    ldsm4(bh, base + WH_OFF + boff);
                    ldsm4(bl, base + WH_OFF + (uint32_t)(NEXP * TPAD * 2) + boff);
                    #pragma unroll
                    for (int mt = 0; mt < 2; ++mt) {
                        mma16816(acc[mt][2 * nt],     ah[mt], bh[0], bh[1]);
                        mma16816(acc[mt][2 * nt],     al[mt], bh[0], bh[1]);
                        mma16816(acc[mt][2 * nt],     ah[mt], bl[0], bl[1]);
                        mma16816(acc[mt][2 * nt + 1], ah[mt], bh[2], bh[3]);
                        mma16816(acc[mt][2 * nt + 1], al[mt], bh[2], bh[3]);
                        mma16816(acc[mt][2 * nt + 1], ah[mt], bl[2], bl[3]);
                    }
                }
            }
        }

        if (kt < HDIM) {
            char* buf = smem + (p ^ 1) * BUF_BYTES;
            #pragma unroll
            for (int jj = 0; jj < 2; ++jj) {
                float4 a = xv[2 * jj], b = xv[2 * jj + 1];
                uint4 hv, lv;
                split2(a.x, a.y, hv.x, lv.x); split2(a.z, a.w, hv.y, lv.y);
                split2(b.x, b.y, hv.z, lv.z); split2(b.z, b.w, hv.w, lv.w);
                const int off = (xr * TPAD + xc + 8 * jj) * 2;
                *(uint4*)(buf + XH_OFF + off) = hv;
                *(uint4*)(buf + XL_OFF + off) = lv;
            }
            asm volatile("cp.async.wait_group 0;" ::: "memory");
            __syncthreads();
            p ^= 1;
        }
    }

    __syncthreads();   // all MMA smem reads done before logits alias buffers

    // ---- two-phase merge of warp-pair partials into padded smem ----
    float* cs = (float*)smem;                 // [BM][65]
    const float inv64 = 0.015625f;
    const int qr = lane >> 2;
    const int qc = (lane & 3) * 2;
    if (warp >= 8) {
        #pragma unroll
        for (int mt = 0; mt < 2; ++mt)
            #pragma unroll
            for (int j = 0; j < 4; ++j) {
                const int row = m0 + mt * 16 + qr;
                const int col = n0 + j * 8 + qc;
                cs[row * 65 + col]           = acc[mt][j][0] * inv64;
                cs[row * 65 + col + 1]       = acc[mt][j][1] * inv64;
                cs[(row + 8) * 65 + col]     = acc[mt][j][2] * inv64;
                cs[(row + 8) * 65 + col + 1] = acc[mt][j][3] * inv64;
            }
    }
    __syncthreads();
    if (warp < 8) {
        #pragma unroll
        for (int mt = 0; mt < 2; ++mt)
            #pragma unroll
            for (int j = 0; j < 4; ++j) {
                const int row = m0 + mt * 16 + qr;
                const int col = n0 + j * 8 + qc;
                cs[row * 65 + col]           += acc[mt][j][0] * inv64;
                cs[row * 65 + col + 1]       += acc[mt][j][1] * inv64;
                cs[(row + 8) * 65 + col]     += acc[mt][j][2] * inv64;
                cs[(row + 8) * 65 + col + 1] += acc[mt][j][3] * inv64;
            }
    }
    __syncthreads();

    // ---- per-token top-2 / softmax / z partial (threads 0..127) ----
    if (tid < BM) {
        const float* row = &cs[tid * 65];
        float m1 = -3.4e38f, m2 = -3.4e38f;
        int i1 = 0, i2 = 0;
        #pragma unroll
        for (int e = 0; e < NEXP; ++e) {
            const float v = row[e];
            if (v > m1)      { m2 = m1; i2 = i1; m1 = v; i1 = e; }
            else if (v > m2) { m2 = v; i2 = e; }
        }
        float ssum = 0.f, sq = 0.f;
        #pragma unroll
        for (int e = 0; e < NEXP; ++e) {
            const float v = row[e];
            ssum += expf(v - m1);
            sq = fmaf(v, v, sq);
        }
        const int gi = tok0 + tid;
        const float inv = 1.0f / ssum;
        out[2 * gi + 0] = (float)i1;
        out[2 * gi + 1] = (float)i2;
        out[2 * T + 2 * gi + 0] = inv;
        out[2 * T + 2 * gi + 1] = expf(m2 - m1) * inv;
        zred[tid] = sq;
    }
    __syncthreads();

    // ---- deterministic z_loss ----
    if (tid == 0) {
        float s = 0.f;
        #pragma unroll
        for (int i = 0; i < BM; ++i) s += zred[i];
        g_z[blockIdx.x] = s;
        __threadfence();
        const unsigned t = atomicAdd(&g_cnt, 1);
        if (t == gridDim.x - 1) {
            float z = 0.f;
            for (unsigned i = 0; i < gridDim.x; ++i) z += g_z[i];
            out[4 * T + 0] = 0.0f;
            out[4 * T + 1] = z / ((float)T * (float)NEXP);
            g_cnt = 0;
        }
    }
}

extern "C" void kernel_launch(void* const* d_in, const int* in_sizes, int n_in,
                              void* d_out, int out_size) {
    const float* X = (const float*)d_in[0];
    const float* W = (const float*)d_in[1];
    float* out = (float*)d_out;
    const int T = in_sizes[0] / HDIM;     // 16384
    prep_w<<<NCHUNK, 256>>>(W);
    cudaFuncSetAttribute(router_mma, cudaFuncAttributeMaxDynamicSharedMemorySize, SMEM_TOTAL);
    router_mma<<<T / BM, NTHR, SMEM_TOTAL>>>(X, out, T);
}